// round 17
// baseline (speedup 1.0000x reference)
#include <cuda_runtime.h>
#include <cuda_fp16.h>
#include <stdint.h>

// ---------------------------------------------------------------------------
// Problem constants: x[32,64,112,112] f32, conv 3x3 pad1 stride1, 64->64 ch.
// ---------------------------------------------------------------------------
#define NB    32
#define CH    64
#define HH_   112
#define WW_   112
#define HW    12544      // 112*112
#define NHW   401408     // 32*112*112
#define NPAIR 1792
#define THR   0.6f

// t-row in smem ring: 136 pixels * 64 ci * 2B (fp16), SW128 swizzled.
#define ROW_BYTES  17408            // 136*128
#define ROW_U4     1088

#define SWZ(o) ((o) ^ (((o) >> 3) & 0x70))

__device__ __align__(16) __half g_w[9 * 64 * 64];   // swizzled shift tiles
__device__ float2 g_part[CH * NB];
__device__ float  g_sa[CH];     // rstd*gamma
__device__ float  g_sb[CH];     // beta - mean*rstd*gamma

// ---------------------------------------------------------------------------
static __device__ __forceinline__ uint32_t smem_u32(const void* p) {
    uint32_t a;
    asm("{ .reg .u64 t; cvta.to.shared.u64 t, %1; cvt.u32.u64 %0, t; }"
        : "=r"(a) : "l"(p));
    return a;
}
static __device__ __forceinline__ void cp16(uint32_t daddr, const void* g) {
    asm volatile("cp.async.cg.shared.global [%0], [%1], 16;"
                 :: "r"(daddr), "l"(g));
}
#define CP_COMMIT() asm volatile("cp.async.commit_group;" ::: "memory")
#define CP_WAIT0()  asm volatile("cp.async.wait_group 0;" ::: "memory")

// ---------------------------------------------------------------------------
// k0: conv_w [co][ci][kh][kw] f32 -> g_w[s][co][ci] fp16, SW128-swizzled tiles
// ---------------------------------------------------------------------------
__global__ void k_wprep(const float* __restrict__ w) {
    int i = blockIdx.x * blockDim.x + threadIdx.x;
    if (i < 9 * 64 * 64) {
        int co = i / 576;
        int r  = i % 576;
        int ci = r / 9;
        int s  = r % 9;            // kh*3 + kw
        int pos = s * 4096 + (SWZ(co * 128 + ci * 2) >> 1);
        g_w[pos] = __float2half(w[i]);
    }
}

// ---------------------------------------------------------------------------
// k1a: per-(c,n) plane partial sums (float4 loads for MLP)
// ---------------------------------------------------------------------------
__global__ void k_stats1(const float* __restrict__ x) {
    int b = blockIdx.x;
    int c = b >> 5, n = b & 31;
    const float4* xp = (const float4*)(x + (size_t)(n * 64 + c) * HW);
    float s = 0.f, s2 = 0.f;
    for (int i = threadIdx.x; i < HW / 4; i += 256) {
        float4 v = xp[i];
        s  += v.x + v.y + v.z + v.w;
        s2 += v.x * v.x + v.y * v.y + v.z * v.z + v.w * v.w;
    }
    __shared__ float rs[256], rq[256];
    rs[threadIdx.x] = s; rq[threadIdx.x] = s2;
    __syncthreads();
    for (int o = 128; o > 0; o >>= 1) {
        if (threadIdx.x < o) {
            rs[threadIdx.x] += rs[threadIdx.x + o];
            rq[threadIdx.x] += rq[threadIdx.x + o];
        }
        __syncthreads();
    }
    if (threadIdx.x == 0) g_part[c * 32 + n] = make_float2(rs[0], rq[0]);
}

// ---------------------------------------------------------------------------
// k1b: deterministic final reduce -> fused scale/shift
// ---------------------------------------------------------------------------
__global__ void k_stats2(const float* __restrict__ gamma,
                         const float* __restrict__ beta) {
    int c = threadIdx.x;
    if (c < 64) {
        double S = 0.0, S2 = 0.0;
        for (int n = 0; n < 32; n++) {
            float2 p = g_part[c * 32 + n];
            S += (double)p.x; S2 += (double)p.y;
        }
        double m   = S / (double)NHW;
        double var = S2 / (double)NHW - m * m;
        float rstd = (float)(1.0 / sqrt(var + 1e-4));
        float sa = rstd * gamma[c];
        g_sa[c] = sa;
        g_sb[c] = beta[c] - (float)m * sa;
    }
}

// ---------------------------------------------------------------------------
// k2: FUSED quant + conv, persistent. Production interleaved with the MMA
//   shift loop. Producer: 2 px/thread via LDG.64 (halves production L1
//   wavefronts), 4-ci chunks to cap the register peak.
//   Conv: warp tile 32px x 32co (R12 shape), epilogue from registers.
// ---------------------------------------------------------------------------
#define BIAS_OFF 0
#define SA_OFF   256
#define SB_OFF   512
#define CSR_OFF  768                      // 6 x 128 float2 = 6144 B
#define BBUF_OFF (CSR_OFF + 6144)         // 6912
#define W_OFF    8192                     // 73728 bytes
#define RING_OFF (8192 + 73728)           // 81920 (1024-aligned)
#define SMEM_TOT (RING_OFF + 6 * ROW_BYTES)   // 186368
#define NCTA     148
#define NTHR     512

static __device__ __forceinline__ void ldsm_x4(uint32_t* r, uint32_t addr) {
    asm volatile("ldmatrix.sync.aligned.m8n8.x4.shared.b16 {%0,%1,%2,%3}, [%4];"
                 : "=r"(r[0]), "=r"(r[1]), "=r"(r[2]), "=r"(r[3]) : "r"(addr));
}
static __device__ __forceinline__ void mma16816(float* d, const uint32_t* a,
                                                const uint32_t* b) {
    asm volatile(
        "mma.sync.aligned.m16n8k16.row.col.f32.f16.f16.f32 "
        "{%0,%1,%2,%3}, {%4,%5,%6,%7}, {%8,%9}, {%0,%1,%2,%3};"
        : "+f"(d[0]), "+f"(d[1]), "+f"(d[2]), "+f"(d[3])
        : "r"(a[0]), "r"(a[1]), "r"(a[2]), "r"(a[3]), "r"(b[0]), "r"(b[1]));
}

__global__ void __launch_bounds__(NTHR, 1)
k_conv(const float* __restrict__ x, const float* __restrict__ convb,
       const float* __restrict__ bbp, float* __restrict__ out) {
    extern __shared__ unsigned char smem[];
    uint32_t sb = smem_u32(smem);
    int tid = threadIdx.x, wid = tid >> 5, lane = tid & 31;

    int P0 = (int)(((long long)blockIdx.x * NPAIR) / NCTA);
    int P1 = (int)(((long long)(blockIdx.x + 1) * NPAIR) / NCTA);

    // Stage weights ONCE (pre-swizzled): 4608 uint4 via cp.async
    for (int i = tid; i < 4608; i += NTHR)
        cp16(sb + W_OFF + i * 16, (const char*)g_w + i * 16);
    CP_COMMIT();
    if (tid < 64) {
        ((float*)(smem + BIAS_OFF))[tid] = convb[tid];
        ((float*)(smem + SA_OFF))[tid]   = g_sa[tid];
        ((float*)(smem + SB_OFF))[tid]   = g_sb[tid];
    }
    // Zero entire ring once (padding bp=0 and bp>=113 stays zero forever)
    {
        uint4 z = make_uint4(0, 0, 0, 0);
        uint4* d = (uint4*)(smem + RING_OFF);
        for (int i = tid; i < 6 * ROW_U4; i += NTHR) d[i] = z;
    }
    CP_WAIT0();
    __syncthreads();

    const float* s_sa = (const float*)(smem + SA_OFF);
    const float* s_sb = (const float*)(smem + SB_OFF);
    float2* csr = (float2*)(smem + CSR_OFF);   // [slot][128] (csum, cnum)
    float* bbf = (float*)(smem + BBUF_OFF);    // 2 rows x 128 px
    const float* bias = (const float*)(smem + BIAS_OFF);
    float bb = bbp[0];

    int qd = tid & 3, pq = tid >> 2;   // producer: 2 px/thread, 16 ci/thread

    // Quantize row r of image nn into ring slot (r+6)%6 (t + csum/cnum).
    // LDG.64 (two adjacent pixels), 4-ci chunks keep the register peak low.
    auto produce_row = [&](int nn, int r) {
        uint32_t slot = (uint32_t)(r + 6) % 6u;
        unsigned char* ts = smem + RING_OFF + slot * ROW_BYTES;
        if (r < 0 || r >= HH_) {
            uint4 z = make_uint4(0, 0, 0, 0);
            for (int i = tid; i < 896; i += NTHR) {   // bp 1..112, 8 cg each
                int bp = 1 + (i >> 3), cg = i & 7;
                *(uint4*)(ts + SWZ((uint32_t)(bp * 128 + cg * 16))) = z;
            }
            return;
        }
        if (pq >= 56) return;
        int px0 = pq * 2;
        const float* xb = x + (size_t)nn * (64 * HW)
                        + (size_t)(qd * 16) * HW + r * WW_ + px0;
        float cs0 = 0.f, cn0 = 0.f, cs1 = 0.f, cn1 = 0.f;
        uint32_t off0 = (uint32_t)(px0 + 1) * 128u + (uint32_t)qd * 32u;
        #pragma unroll
        for (int chk = 0; chk < 4; chk++) {
            float2 v[4];
            #pragma unroll
            for (int i = 0; i < 4; i++)
                v[i] = *(const float2*)(xb + (size_t)(chk * 4 + i) * HW);
            uint32_t pa[2], pb[2];
            #pragma unroll
            for (int j = 0; j < 2; j++) {
                int c0 = qd * 16 + chk * 4 + 2 * j;
                float sa0 = s_sa[c0],     sb0 = s_sb[c0];
                float sa1 = s_sa[c0 + 1], sb1 = s_sb[c0 + 1];
                // pixel px0 (.x lanes)
                float xa0 = fminf(fmaxf(fmaf(v[2*j].x,   sa0, sb0), -1.f), 1.f);
                float xa1 = fminf(fmaxf(fmaf(v[2*j+1].x, sa1, sb1), -1.f), 1.f);
                float ta0 = (xa0 >= THR) ? 1.f : ((xa0 <= -THR) ? -1.f : 0.f);
                float ta1 = (xa1 >= THR) ? 1.f : ((xa1 <= -THR) ? -1.f : 0.f);
                cs0 = fmaf(xa0, ta0, cs0); cs0 = fmaf(xa1, ta1, cs0);
                cn0 = fmaf(ta0, ta0, cn0); cn0 = fmaf(ta1, ta1, cn0);
                __half2 ha = __floats2half2_rn(ta0, ta1);
                pa[j] = *(uint32_t*)&ha;
                // pixel px0+1 (.y lanes)
                float xb0 = fminf(fmaxf(fmaf(v[2*j].y,   sa0, sb0), -1.f), 1.f);
                float xb1 = fminf(fmaxf(fmaf(v[2*j+1].y, sa1, sb1), -1.f), 1.f);
                float tb0 = (xb0 >= THR) ? 1.f : ((xb0 <= -THR) ? -1.f : 0.f);
                float tb1 = (xb1 >= THR) ? 1.f : ((xb1 <= -THR) ? -1.f : 0.f);
                cs1 = fmaf(xb0, tb0, cs1); cs1 = fmaf(xb1, tb1, cs1);
                cn1 = fmaf(tb0, tb0, cn1); cn1 = fmaf(tb1, tb1, cn1);
                __half2 hb = __floats2half2_rn(tb0, tb1);
                pb[j] = *(uint32_t*)&hb;
            }
            *(uint2*)(ts + SWZ(off0 + chk * 8))        = make_uint2(pa[0], pa[1]);
            *(uint2*)(ts + SWZ(off0 + 128u + chk * 8)) = make_uint2(pb[0], pb[1]);
        }
        cs0 += __shfl_xor_sync(0xFFFFFFFFu, cs0, 1);
        cs0 += __shfl_xor_sync(0xFFFFFFFFu, cs0, 2);
        cn0 += __shfl_xor_sync(0xFFFFFFFFu, cn0, 1);
        cn0 += __shfl_xor_sync(0xFFFFFFFFu, cn0, 2);
        cs1 += __shfl_xor_sync(0xFFFFFFFFu, cs1, 1);
        cs1 += __shfl_xor_sync(0xFFFFFFFFu, cs1, 2);
        cn1 += __shfl_xor_sync(0xFFFFFFFFu, cn1, 1);
        cn1 += __shfl_xor_sync(0xFFFFFFFFu, cn1, 2);
        if (qd == 0)
            *(float4*)&csr[slot * 128 + px0] = make_float4(cs0, cn0, cs1, cn1);
    };

    // Conv fragment maps (R12 shape): 16 warps, tile 32px x 32co
    int rowsel = wid >> 3, wm = (wid >> 1) & 3, wn = wid & 1;
    int rA    = wm * 32 + (lane & 15);
    int kaddA = (lane >> 4) * 16;
    int rowB2  = wn * 32 + ((lane >> 4) << 3) + (lane & 7);
    int kaddB2 = ((lane >> 3) & 1) * 16;
    int g = lane >> 2, cq = (lane & 3) * 2;
    int r2a = (tid >> 7) & 1, px = tid & 127;   // beta map (tid<256 only)

    for (int P = P0; P < P1; P++) {
        int n = P / 56, h = (P % 56) * 2;
        bool pf = (P + 1 < P1) && (h < HH_ - 2);

        // Prime: produce this pair's 4 input rows, then publish.
        if (P == P0 || h == 0) {
            produce_row(n, h - 1);
            produce_row(n, h);
            produce_row(n, h + 1);
            produce_row(n, h + 2);
            __syncthreads();
        }

        float acc[2][4][4];
        #pragma unroll
        for (int mt = 0; mt < 2; mt++)
            #pragma unroll
            for (int j = 0; j < 4; j++)
                #pragma unroll
                for (int v = 0; v < 4; v++) acc[mt][j][v] = 0.f;

        // ---- Interleave 1: produce next-pair row h+3 (no barrier) ----
        if (pf) produce_row(n, h + 3);

        // ---- MMA shifts s = 0..3 ----
        #pragma unroll
        for (int s = 0; s < 4; s++) {
            int kh = s / 3, kw = s % 3;
            uint32_t slot = (uint32_t)(h + rowsel + kh + 5) % 6u;
            uint32_t abase = sb + RING_OFF + slot * ROW_BYTES;
            uint32_t bbase = sb + W_OFF + s * 8192;
            #pragma unroll
            for (int c = 0; c < 4; c++) {
                uint32_t bf[8];
                #pragma unroll
                for (int q = 0; q < 2; q++) {
                    uint32_t off = (uint32_t)(rowB2 + 16 * q) * 128u
                                 + (uint32_t)c * 32u + kaddB2;
                    ldsm_x4(&bf[q * 4], bbase + SWZ(off));
                }
                uint32_t a[2][4];
                #pragma unroll
                for (int mt = 0; mt < 2; mt++) {
                    uint32_t off = (uint32_t)(rA + mt * 16 + kw) * 128u
                                 + (uint32_t)c * 32u + kaddA;
                    ldsm_x4(a[mt], abase + SWZ(off));
                }
                #pragma unroll
                for (int mt = 0; mt < 2; mt++)
                    #pragma unroll
                    for (int j = 0; j < 4; j++)
                        mma16816(acc[mt][j], a[mt],
                                 &bf[(j >> 1) * 4 + (j & 1) * 2]);
            }
        }

        // ---- Interleave 2: produce row h+4 + beta gather ----
        if (pf) produce_row(n, h + 4);

        float bs = 0.f, bn = 0.f;
        if (tid < 256 && px < WW_) {
            int hb = h + r2a;
            #pragma unroll
            for (int dh = -1; dh <= 1; dh++) {
                int hh = hb + dh;
                if ((unsigned)hh >= (unsigned)HH_) continue;
                int sl = hh % 6;
                #pragma unroll
                for (int dw = -1; dw <= 1; dw++) {
                    int ww = px + dw;
                    if ((unsigned)ww >= (unsigned)WW_) continue;
                    float2 v = csr[sl * 128 + ww];
                    bs += v.x;
                    bn += v.y;
                }
            }
        }

        // ---- MMA shifts s = 4..8 ----
        #pragma unroll
        for (int s = 4; s < 9; s++) {
            int kh = s / 3, kw = s % 3;
            uint32_t slot = (uint32_t)(h + rowsel + kh + 5) % 6u;
            uint32_t abase = sb + RING_OFF + slot * ROW_BYTES;
            uint32_t bbase = sb + W_OFF + s * 8192;
            #pragma unroll
            for (int c = 0; c < 4; c++) {
                uint32_t bf[8];
                #pragma unroll
                for (int q = 0; q < 2; q++) {
                    uint32_t off = (uint32_t)(rowB2 + 16 * q) * 128u
                                 + (uint32_t)c * 32u + kaddB2;
                    ldsm_x4(&bf[q * 4], bbase + SWZ(off));
                }
                uint32_t a[2][4];
                #pragma unroll
                for (int mt = 0; mt < 2; mt++) {
                    uint32_t off = (uint32_t)(rA + mt * 16 + kw) * 128u
                                 + (uint32_t)c * 32u + kaddA;
                    ldsm_x4(a[mt], abase + SWZ(off));
                }
                #pragma unroll
                for (int mt = 0; mt < 2; mt++)
                    #pragma unroll
                    for (int j = 0; j < 4; j++)
                        mma16816(acc[mt][j], a[mt],
                                 &bf[(j >> 1) * 4 + (j & 1) * 2]);
            }
        }

        // ---- Publish per-pixel beta ----
        if (tid < 256 && px < WW_) {
            float cnt = bn + bb;
            if (cnt == 0.f) cnt = 1.f;
            bbf[r2a * 128 + px] = (bs + bb) / cnt;
        }
        __syncthreads();

        // ---- Epilogue direct from registers ----
        {
            int row = h + rowsel;
            float* ob = out + (size_t)n * (64 * HW) + row * WW_;
            #pragma unroll
            for (int mt = 0; mt < 2; mt++) {
                int pbase = wm * 32 + mt * 16 + g;
                #pragma unroll
                for (int hf = 0; hf < 2; hf++) {
                    int pp = pbase + hf * 8;
                    if (pp < WW_) {
                        float betav = bbf[rowsel * 128 + pp];
                        #pragma unroll
                        for (int j = 0; j < 4; j++) {
                            int co = wn * 32 + j * 8 + cq;
                            ob[(size_t)co * HW + pp] =
                                (acc[mt][j][hf * 2] + bias[co]) * betav;
                            ob[(size_t)(co + 1) * HW + pp] =
                                (acc[mt][j][hf * 2 + 1] + bias[co + 1]) * betav;
                        }
                    }
                }
            }
        }
        __syncthreads();   // publish produced rows; bbuf/ring reuse safe
    }
}

// ---------------------------------------------------------------------------
extern "C" void kernel_launch(void* const* d_in, const int* in_sizes, int n_in,
                              void* d_out, int out_size) {
    const float* x     = (const float*)d_in[0];
    const float* gamma = (const float*)d_in[1];
    const float* beta  = (const float*)d_in[2];
    const float* cw    = (const float*)d_in[3];
    const float* cb    = (const float*)d_in[4];
    const float* bb    = (const float*)d_in[5];
    float* out = (float*)d_out;

    cudaFuncSetAttribute(k_conv, cudaFuncAttributeMaxDynamicSharedMemorySize, SMEM_TOT);

    k_wprep<<<288, 128>>>(cw);
    k_stats1<<<2048, 256>>>(x);
    k_stats2<<<1, 64>>>(gamma, beta);
    k_conv<<<NCTA, NTHR, SMEM_TOT>>>(x, cb, bb, out);
}